// round 15
// baseline (speedup 1.0000x reference)
#include <cuda_runtime.h>
#include <cuda_bf16.h>

// FocalLoss: input [N,C]=[1048576,80] fp32, target [N] int32, gamma=2.
// out = mean_n sum_c -(1-pt)^2*logpt, pt = sigmoid(sign*x).
//
// R15 = R14 (57.4us, ~99% of observed DRAM ceiling) with the streaming loads
// widened to 256-bit (LDG.256 / ld.global.nc.v8.f32, Blackwell): 5 loads per
// 16-row tile instead of 10 -> half the L1tex queue entries, deeper MLP.
// Core: pt = 0.5 + 0.5*tanh(x/2); contribution = (1-pt)^2*log2(pt) (negative,
// log2 space); 2 MUFU + 5 fma-pipe ops per element. Evict-first hints on the
// read-once stream; correction gather stays on the default cache path.

#define N_ROWS   1048576
#define C_CLS    80
#define ROWS_PER_TILE 16
#define F8_PER_TILE   160          // 16 rows * 80 floats = 160 float8
#define N_TILES  (N_ROWS / ROWS_PER_TILE)   // 65536
#define NBLOCKS  1184              // 148 SMs * 8 CTAs, single wave
#define NTHREADS 256
#define WARPS_PER_BLOCK (NTHREADS / 32)
#define LN2      0.6931471805599453

__device__ double g_partials[NBLOCKS];
__device__ unsigned int g_count;

__device__ __forceinline__ float tanhf_(float x) {
    float y; asm("tanh.approx.f32 %0, %1;" : "=f"(y) : "f"(x)); return y;
}
__device__ __forceinline__ float lg2f_(float x) {
    float y; asm("lg2.approx.f32 %0, %1;" : "=f"(y) : "f"(x)); return y;
}

// 256-bit read-once streaming load (sm_100+): evict-first, non-coherent.
__device__ __forceinline__ void ldg_stream8(const float* p, float* v) {
    asm volatile(
        "ld.global.nc.L1::no_allocate.v8.f32 {%0,%1,%2,%3,%4,%5,%6,%7}, [%8];"
        : "=f"(v[0]), "=f"(v[1]), "=f"(v[2]), "=f"(v[3]),
          "=f"(v[4]), "=f"(v[5]), "=f"(v[6]), "=f"(v[7])
        : "l"(p));
}

// core_h(h) with h = x/2: returns (1-pt)^2 * log2(pt)  (negative).
__device__ __forceinline__ float focal_core_h(float h) {
    float t  = tanhf_(h);                    // MUFU.TANH
    float q  = fmaf(-0.5f, t, 0.5f);         // 1-pt = sigma(-x)
    float pt = fmaf( 0.5f, t, 0.5f);         // sigma(x)
    float pp = q * q;
    return pp * lg2f_(pt);                   // MUFU.LG2; folds to FFMA w/ acc
}

__global__ __launch_bounds__(NTHREADS, 8) void focal_fused_kernel(
    const float* __restrict__ inp,
    const int* __restrict__ tgt,
    float* __restrict__ out)
{
    const unsigned lane   = threadIdx.x & 31u;
    const unsigned gwarp  = blockIdx.x * WARPS_PER_BLOCK + (threadIdx.x >> 5);
    const unsigned nwarps = gridDim.x * WARPS_PER_BLOCK;   // 9472

    float fs0 = 0.0f, fs1 = 0.0f;    // negative log2-space accumulators

    for (unsigned tile = gwarp; tile < (unsigned)N_TILES; tile += nwarps) {
        const unsigned row0  = tile * ROWS_PER_TILE;
        const unsigned base8 = tile * (unsigned)F8_PER_TILE + lane;  // float8 idx

        // stage 1: issue target-index load early (lanes 0-15 own one row each)
        int t = 0;
        if (lane < 16u) t = __ldg(&tgt[row0 + lane]);

        float v[8];
        // non-target element v: x = -v -> h = -v/2
        #pragma unroll 3
        for (unsigned k = 0; k < 3u; k++) {
            ldg_stream8(inp + (base8 + k * 32u) * 8u, v);
            fs0 += focal_core_h(v[0] * -0.5f);
            fs1 += focal_core_h(v[1] * -0.5f);
            fs0 += focal_core_h(v[2] * -0.5f);
            fs1 += focal_core_h(v[3] * -0.5f);
            fs0 += focal_core_h(v[4] * -0.5f);
            fs1 += focal_core_h(v[5] * -0.5f);
            fs0 += focal_core_h(v[6] * -0.5f);
            fs1 += focal_core_h(v[7] * -0.5f);
        }

        // stage 2: dependent gather; default cache path (line is L2-resident)
        float tv = 0.0f;
        if (lane < 16u)
            tv = __ldg(&inp[(row0 + lane) * (unsigned)C_CLS + (unsigned)t]);

        #pragma unroll 2
        for (unsigned k = 3u; k < 5u; k++) {
            ldg_stream8(inp + (base8 + k * 32u) * 8u, v);
            fs0 += focal_core_h(v[0] * -0.5f);
            fs1 += focal_core_h(v[1] * -0.5f);
            fs0 += focal_core_h(v[2] * -0.5f);
            fs1 += focal_core_h(v[3] * -0.5f);
            fs0 += focal_core_h(v[4] * -0.5f);
            fs1 += focal_core_h(v[5] * -0.5f);
            fs0 += focal_core_h(v[6] * -0.5f);
            fs1 += focal_core_h(v[7] * -0.5f);
        }

        // stage 3: correction math (target term uses h=+v/2; remove -v/2 term)
        if (lane < 16u)
            fs0 += focal_core_h(tv * 0.5f) - focal_core_h(tv * -0.5f);
    }

    float fsum = fs0 + fs1;

    #pragma unroll
    for (int off = 16; off > 0; off >>= 1)
        fsum += __shfl_down_sync(0xFFFFFFFFu, fsum, off);

    __shared__ double s_warp[WARPS_PER_BLOCK];
    int wid = threadIdx.x >> 5;
    if (lane == 0) s_warp[wid] = (double)fsum;
    __syncthreads();

    __shared__ bool s_last;
    if (threadIdx.x == 0) {
        double bsum = 0.0;
        #pragma unroll
        for (int w = 0; w < WARPS_PER_BLOCK; w++) bsum += s_warp[w];
        g_partials[blockIdx.x] = bsum;
        __threadfence();
        unsigned done = atomicAdd(&g_count, 1u);
        s_last = (done == gridDim.x - 1);
    }
    __syncthreads();

    if (s_last) {
        __threadfence();
        __shared__ double s_red[NTHREADS];
        double v2 = 0.0;
        for (int k = threadIdx.x; k < NBLOCKS; k += NTHREADS)
            v2 += g_partials[k];
        s_red[threadIdx.x] = v2;
        __syncthreads();
        #pragma unroll
        for (int off = NTHREADS / 2; off > 0; off >>= 1) {
            if (threadIdx.x < off) s_red[threadIdx.x] += s_red[threadIdx.x + off];
            __syncthreads();
        }
        if (threadIdx.x == 0) {
            out[0] = (float)(s_red[0] * -LN2 / (double)N_ROWS);
            g_count = 0;
        }
    }
}

extern "C" void kernel_launch(void* const* d_in, const int* in_sizes, int n_in,
                              void* d_out, int out_size)
{
    const float* inp = (const float*)d_in[0];
    const int* tgt   = (const int*)d_in[1];
    float* out       = (float*)d_out;

    focal_fused_kernel<<<NBLOCKS, NTHREADS>>>(inp, tgt, out);
}

// round 16
// speedup vs baseline: 1.0780x; 1.0780x over previous
#include <cuda_runtime.h>
#include <cuda_bf16.h>

// FocalLoss: input [N,C]=[1048576,80] fp32, target [N] int32, gamma=2.
// out = mean_n sum_c -(1-pt)^2*logpt, pt = sigmoid(sign*x).
//
// R16 = R14 (best, 57.4us = ~99% of the observed 6.06 TB/s DRAM ceiling).
// LDG.256 (R15) regressed and is reverted; 128-bit evict-first streaming
// loads restored. Only delta vs R14: the tgt load also uses the .nc
// streaming path (read-once).
// Core: pt = 0.5 + 0.5*tanh(x/2); contribution = (1-pt)^2*log2(pt)
// (negative, log2 space); 2 MUFU + 5 fma-pipe ops per element.
// 16-row tiles, pipelined correction gather, single-wave 1184x256 grid,
// 32 regs (8 CTA/SM), deterministic last-block double reduction.

#define N_ROWS   1048576
#define C_CLS    80
#define ROWS_PER_TILE 16
#define F4_PER_TILE   320          // 16 rows * 20 float4
#define N_TILES  (N_ROWS / ROWS_PER_TILE)   // 65536
#define NBLOCKS  1184              // 148 SMs * 8 CTAs, single wave
#define NTHREADS 256
#define WARPS_PER_BLOCK (NTHREADS / 32)
#define LN2      0.6931471805599453

__device__ double g_partials[NBLOCKS];
__device__ unsigned int g_count;

__device__ __forceinline__ float tanhf_(float x) {
    float y; asm("tanh.approx.f32 %0, %1;" : "=f"(y) : "f"(x)); return y;
}
__device__ __forceinline__ float lg2f_(float x) {
    float y; asm("lg2.approx.f32 %0, %1;" : "=f"(y) : "f"(x)); return y;
}

// read-once streaming load: non-coherent path + evict-first
__device__ __forceinline__ float4 ldg_stream4(const float4* p) {
    float4 v;
    asm volatile("ld.global.nc.L1::no_allocate.v4.f32 {%0,%1,%2,%3}, [%4];"
                 : "=f"(v.x), "=f"(v.y), "=f"(v.z), "=f"(v.w) : "l"(p));
    return v;
}
__device__ __forceinline__ int ldg_stream_i(const int* p) {
    int v;
    asm volatile("ld.global.nc.L1::no_allocate.b32 %0, [%1];"
                 : "=r"(v) : "l"(p));
    return v;
}

// core_h(h) with h = x/2: returns (1-pt)^2 * log2(pt)  (negative).
__device__ __forceinline__ float focal_core_h(float h) {
    float t  = tanhf_(h);                    // MUFU.TANH
    float q  = fmaf(-0.5f, t, 0.5f);         // 1-pt = sigma(-x)
    float pt = fmaf( 0.5f, t, 0.5f);         // sigma(x)
    float pp = q * q;
    return pp * lg2f_(pt);                   // MUFU.LG2; folds to FFMA w/ acc
}

__global__ __launch_bounds__(NTHREADS, 8) void focal_fused_kernel(
    const float* __restrict__ inp,
    const int* __restrict__ tgt,
    float* __restrict__ out)
{
    const unsigned lane   = threadIdx.x & 31u;
    const unsigned gwarp  = blockIdx.x * WARPS_PER_BLOCK + (threadIdx.x >> 5);
    const unsigned nwarps = gridDim.x * WARPS_PER_BLOCK;   // 9472

    const float4* __restrict__ inp4 = (const float4*)inp;

    float fs0 = 0.0f, fs1 = 0.0f;    // negative log2-space accumulators

    for (unsigned tile = gwarp; tile < (unsigned)N_TILES; tile += nwarps) {
        const unsigned row0 = tile * ROWS_PER_TILE;
        const unsigned base = tile * (unsigned)F4_PER_TILE + lane;

        // stage 1: issue target-index load early (lanes 0-15 own one row each)
        int t = 0;
        if (lane < 16u) t = ldg_stream_i(&tgt[row0 + lane]);

        // non-target element v: x = -v -> h = -v/2
        #pragma unroll 5
        for (unsigned k = 0; k < 5u; k++) {
            float4 v = ldg_stream4(&inp4[base + k * 32u]);
            fs0 += focal_core_h(v.x * -0.5f);
            fs1 += focal_core_h(v.y * -0.5f);
            fs0 += focal_core_h(v.z * -0.5f);
            fs1 += focal_core_h(v.w * -0.5f);
        }

        // stage 2: dependent gather; default cache path (line is L2-resident)
        float tv = 0.0f;
        if (lane < 16u)
            tv = __ldg(&inp[(row0 + lane) * (unsigned)C_CLS + (unsigned)t]);

        #pragma unroll 5
        for (unsigned k = 5u; k < 10u; k++) {
            float4 v = ldg_stream4(&inp4[base + k * 32u]);
            fs0 += focal_core_h(v.x * -0.5f);
            fs1 += focal_core_h(v.y * -0.5f);
            fs0 += focal_core_h(v.z * -0.5f);
            fs1 += focal_core_h(v.w * -0.5f);
        }

        // stage 3: correction math (target term uses h=+v/2; remove -v/2 term)
        if (lane < 16u)
            fs0 += focal_core_h(tv * 0.5f) - focal_core_h(tv * -0.5f);
    }

    float fsum = fs0 + fs1;

    #pragma unroll
    for (int off = 16; off > 0; off >>= 1)
        fsum += __shfl_down_sync(0xFFFFFFFFu, fsum, off);

    __shared__ double s_warp[WARPS_PER_BLOCK];
    int wid = threadIdx.x >> 5;
    if (lane == 0) s_warp[wid] = (double)fsum;
    __syncthreads();

    __shared__ bool s_last;
    if (threadIdx.x == 0) {
        double bsum = 0.0;
        #pragma unroll
        for (int w = 0; w < WARPS_PER_BLOCK; w++) bsum += s_warp[w];
        g_partials[blockIdx.x] = bsum;
        __threadfence();
        unsigned done = atomicAdd(&g_count, 1u);
        s_last = (done == gridDim.x - 1);
    }
    __syncthreads();

    if (s_last) {
        __threadfence();
        __shared__ double s_red[NTHREADS];
        double v = 0.0;
        for (int k = threadIdx.x; k < NBLOCKS; k += NTHREADS)
            v += g_partials[k];
        s_red[threadIdx.x] = v;
        __syncthreads();
        #pragma unroll
        for (int off = NTHREADS / 2; off > 0; off >>= 1) {
            if (threadIdx.x < off) s_red[threadIdx.x] += s_red[threadIdx.x + off];
            __syncthreads();
        }
        if (threadIdx.x == 0) {
            out[0] = (float)(s_red[0] * -LN2 / (double)N_ROWS);
            g_count = 0;
        }
    }
}

extern "C" void kernel_launch(void* const* d_in, const int* in_sizes, int n_in,
                              void* d_out, int out_size)
{
    const float* inp = (const float*)d_in[0];
    const int* tgt   = (const int*)d_in[1];
    float* out       = (float*)d_out;

    focal_fused_kernel<<<NBLOCKS, NTHREADS>>>(inp, tgt, out);
}

// round 17
// speedup vs baseline: 1.0811x; 1.0028x over previous
#include <cuda_runtime.h>
#include <cuda_bf16.h>

// FocalLoss: input [N,C]=[1048576,80] fp32, target [N] int32, gamma=2.
// out = mean_n sum_c -(1-pt)^2*logpt, pt = sigmoid(sign*x).
//
// FINAL (R16 confirmation re-bench, 57.0us = ~99.5% of the observed
// 6.06 TB/s DRAM ceiling; memory floor for 344 MB is 56.8us).
//
// Design summary (evidence-driven across 16 rounds):
//  - Streaming main loop with ZERO per-element target logic; per-tile
//    correction adds F(v_t)-F(-v_t) via an L2-resident gather issued
//    mid-stream (software-pipelined under the remaining loads).
//  - Core on MUFU.TANH: pt = 0.5+0.5*tanh(x/2); per-element contribution
//    (1-pt)^2*log2(pt) in log2 space; *ln2 applied once at the end.
//    2 MUFU + 5 fma-pipe ops/elem. (Newton/Halley reciprocal and f32x2
//    variants measured slower; LDG.256 measured slower.)
//  - 128-bit evict-first streaming loads (ld.global.nc.L1::no_allocate).
//  - 16-row tiles: 6.92 tiles/warp -> 1.2% tail (32-row had 16% tail).
//  - 1184x256 grid = exactly one resident wave at 32 regs (8 CTA/SM);
//    wave quantization previously cost 8us.
//  - Deterministic reduction: block partials in double -> last-block
//    (atomic counter, self-resetting for graph replay) fixed-order sum.

#define N_ROWS   1048576
#define C_CLS    80
#define ROWS_PER_TILE 16
#define F4_PER_TILE   320          // 16 rows * 20 float4
#define N_TILES  (N_ROWS / ROWS_PER_TILE)   // 65536
#define NBLOCKS  1184              // 148 SMs * 8 CTAs, single wave
#define NTHREADS 256
#define WARPS_PER_BLOCK (NTHREADS / 32)
#define LN2      0.6931471805599453

__device__ double g_partials[NBLOCKS];
__device__ unsigned int g_count;

__device__ __forceinline__ float tanhf_(float x) {
    float y; asm("tanh.approx.f32 %0, %1;" : "=f"(y) : "f"(x)); return y;
}
__device__ __forceinline__ float lg2f_(float x) {
    float y; asm("lg2.approx.f32 %0, %1;" : "=f"(y) : "f"(x)); return y;
}

// read-once streaming load: non-coherent path + evict-first
__device__ __forceinline__ float4 ldg_stream4(const float4* p) {
    float4 v;
    asm volatile("ld.global.nc.L1::no_allocate.v4.f32 {%0,%1,%2,%3}, [%4];"
                 : "=f"(v.x), "=f"(v.y), "=f"(v.z), "=f"(v.w) : "l"(p));
    return v;
}
__device__ __forceinline__ int ldg_stream_i(const int* p) {
    int v;
    asm volatile("ld.global.nc.L1::no_allocate.b32 %0, [%1];"
                 : "=r"(v) : "l"(p));
    return v;
}

// core_h(h) with h = x/2: returns (1-pt)^2 * log2(pt)  (negative).
__device__ __forceinline__ float focal_core_h(float h) {
    float t  = tanhf_(h);                    // MUFU.TANH
    float q  = fmaf(-0.5f, t, 0.5f);         // 1-pt = sigma(-x)
    float pt = fmaf( 0.5f, t, 0.5f);         // sigma(x)
    float pp = q * q;
    return pp * lg2f_(pt);                   // MUFU.LG2; folds to FFMA w/ acc
}

__global__ __launch_bounds__(NTHREADS, 8) void focal_fused_kernel(
    const float* __restrict__ inp,
    const int* __restrict__ tgt,
    float* __restrict__ out)
{
    const unsigned lane   = threadIdx.x & 31u;
    const unsigned gwarp  = blockIdx.x * WARPS_PER_BLOCK + (threadIdx.x >> 5);
    const unsigned nwarps = gridDim.x * WARPS_PER_BLOCK;   // 9472

    const float4* __restrict__ inp4 = (const float4*)inp;

    float fs0 = 0.0f, fs1 = 0.0f;    // negative log2-space accumulators

    for (unsigned tile = gwarp; tile < (unsigned)N_TILES; tile += nwarps) {
        const unsigned row0 = tile * ROWS_PER_TILE;
        const unsigned base = tile * (unsigned)F4_PER_TILE + lane;

        // stage 1: issue target-index load early (lanes 0-15 own one row each)
        int t = 0;
        if (lane < 16u) t = ldg_stream_i(&tgt[row0 + lane]);

        // non-target element v: x = -v -> h = -v/2
        #pragma unroll 5
        for (unsigned k = 0; k < 5u; k++) {
            float4 v = ldg_stream4(&inp4[base + k * 32u]);
            fs0 += focal_core_h(v.x * -0.5f);
            fs1 += focal_core_h(v.y * -0.5f);
            fs0 += focal_core_h(v.z * -0.5f);
            fs1 += focal_core_h(v.w * -0.5f);
        }

        // stage 2: dependent gather; default cache path (line is L2-resident)
        float tv = 0.0f;
        if (lane < 16u)
            tv = __ldg(&inp[(row0 + lane) * (unsigned)C_CLS + (unsigned)t]);

        #pragma unroll 5
        for (unsigned k = 5u; k < 10u; k++) {
            float4 v = ldg_stream4(&inp4[base + k * 32u]);
            fs0 += focal_core_h(v.x * -0.5f);
            fs1 += focal_core_h(v.y * -0.5f);
            fs0 += focal_core_h(v.z * -0.5f);
            fs1 += focal_core_h(v.w * -0.5f);
        }

        // stage 3: correction math (target term uses h=+v/2; remove -v/2 term)
        if (lane < 16u)
            fs0 += focal_core_h(tv * 0.5f) - focal_core_h(tv * -0.5f);
    }

    float fsum = fs0 + fs1;

    #pragma unroll
    for (int off = 16; off > 0; off >>= 1)
        fsum += __shfl_down_sync(0xFFFFFFFFu, fsum, off);

    __shared__ double s_warp[WARPS_PER_BLOCK];
    int wid = threadIdx.x >> 5;
    if (lane == 0) s_warp[wid] = (double)fsum;
    __syncthreads();

    __shared__ bool s_last;
    if (threadIdx.x == 0) {
        double bsum = 0.0;
        #pragma unroll
        for (int w = 0; w < WARPS_PER_BLOCK; w++) bsum += s_warp[w];
        g_partials[blockIdx.x] = bsum;
        __threadfence();
        unsigned done = atomicAdd(&g_count, 1u);
        s_last = (done == gridDim.x - 1);
    }
    __syncthreads();

    if (s_last) {
        __threadfence();
        __shared__ double s_red[NTHREADS];
        double v = 0.0;
        for (int k = threadIdx.x; k < NBLOCKS; k += NTHREADS)
            v += g_partials[k];
        s_red[threadIdx.x] = v;
        __syncthreads();
        #pragma unroll
        for (int off = NTHREADS / 2; off > 0; off >>= 1) {
            if (threadIdx.x < off) s_red[threadIdx.x] += s_red[threadIdx.x + off];
            __syncthreads();
        }
        if (threadIdx.x == 0) {
            out[0] = (float)(s_red[0] * -LN2 / (double)N_ROWS);
            g_count = 0;
        }
    }
}

extern "C" void kernel_launch(void* const* d_in, const int* in_sizes, int n_in,
                              void* d_out, int out_size)
{
    const float* inp = (const float*)d_in[0];
    const int* tgt   = (const int*)d_in[1];
    float* out       = (float*)d_out;

    focal_fused_kernel<<<NBLOCKS, NTHREADS>>>(inp, tgt, out);
}